// round 2
// baseline (speedup 1.0000x reference)
#include <cuda_runtime.h>

// Problem constants (fixed by the dataset)
#define B_ROWS 4096
#define DIM_IN 128
#define H_DIM  512
#define D_DIM  256
#define M_CON  64
#define N_ITER 100
#define TR     32          // rows per block in the iteration kernel

// Scratch (device globals: no allocation allowed)
__device__ float g_h1[B_ROWS * H_DIM];
__device__ float g_h2[B_ROWS * H_DIM];
__device__ float g_y0[B_ROWS * D_DIM];
__device__ float g_Ginv[M_CON * M_CON];
__device__ float g_Mop[M_CON * D_DIM];

// ---------------------------------------------------------------------------
// Classic register-blocked SGEMM: C = act(X @ W + bias)
// BM=BN=128, BK=16, 256 threads, 8x8 per thread. All dims divide tiles.
// ---------------------------------------------------------------------------
__global__ __launch_bounds__(256) void gemm_bias_act(
    const float* __restrict__ X, const float* __restrict__ W,
    const float* __restrict__ bias, float* __restrict__ C,
    int M, int N, int K, int doRelu)
{
    __shared__ float Xs[16][128];
    __shared__ float Ws[16][128];

    const int tid  = threadIdx.x;
    const int brow = blockIdx.y * 128;
    const int bcol = blockIdx.x * 128;
    const int tx   = tid & 15;   // n-dir, 8 cols
    const int ty   = tid >> 4;   // m-dir, 8 rows

    // load mapping
    const int xr0 = tid >> 2;          // 0..63  (+64 for second)
    const int xc0 = (tid & 3) * 4;     // 0,4,8,12
    const int wr0 = tid >> 5;          // 0..7   (+8 for second)
    const int wc0 = (tid & 31) * 4;    // 0..124

    float acc[8][8];
    #pragma unroll
    for (int i = 0; i < 8; i++)
        #pragma unroll
        for (int j = 0; j < 8; j++) acc[i][j] = 0.0f;

    for (int kt = 0; kt < K; kt += 16) {
        float4 xv0 = *(const float4*)&X[(size_t)(brow + xr0) * K + kt + xc0];
        float4 xv1 = *(const float4*)&X[(size_t)(brow + xr0 + 64) * K + kt + xc0];
        float4 wv0 = *(const float4*)&W[(size_t)(kt + wr0) * N + bcol + wc0];
        float4 wv1 = *(const float4*)&W[(size_t)(kt + wr0 + 8) * N + bcol + wc0];

        // transpose-store X tile: Xs[k][m]
        Xs[xc0 + 0][xr0] = xv0.x;  Xs[xc0 + 1][xr0] = xv0.y;
        Xs[xc0 + 2][xr0] = xv0.z;  Xs[xc0 + 3][xr0] = xv0.w;
        Xs[xc0 + 0][xr0 + 64] = xv1.x;  Xs[xc0 + 1][xr0 + 64] = xv1.y;
        Xs[xc0 + 2][xr0 + 64] = xv1.z;  Xs[xc0 + 3][xr0 + 64] = xv1.w;
        *(float4*)&Ws[wr0][wc0]     = wv0;
        *(float4*)&Ws[wr0 + 8][wc0] = wv1;
        __syncthreads();

        #pragma unroll
        for (int k = 0; k < 16; k++) {
            float a[8], b[8];
            float4 a0 = *(const float4*)&Xs[k][ty * 8];
            float4 a1 = *(const float4*)&Xs[k][ty * 8 + 4];
            float4 b0 = *(const float4*)&Ws[k][tx * 8];
            float4 b1 = *(const float4*)&Ws[k][tx * 8 + 4];
            a[0]=a0.x; a[1]=a0.y; a[2]=a0.z; a[3]=a0.w;
            a[4]=a1.x; a[5]=a1.y; a[6]=a1.z; a[7]=a1.w;
            b[0]=b0.x; b[1]=b0.y; b[2]=b0.z; b[3]=b0.w;
            b[4]=b1.x; b[5]=b1.y; b[6]=b1.z; b[7]=b1.w;
            #pragma unroll
            for (int i = 0; i < 8; i++)
                #pragma unroll
                for (int j = 0; j < 8; j++)
                    acc[i][j] = fmaf(a[i], b[j], acc[i][j]);
        }
        __syncthreads();
    }

    #pragma unroll
    for (int i = 0; i < 8; i++) {
        int row = brow + ty * 8 + i;
        #pragma unroll
        for (int j = 0; j < 8; j++) {
            int col = bcol + tx * 8 + j;
            float v = acc[i][j] + bias[col];
            if (doRelu) v = fmaxf(v, 0.0f);
            C[(size_t)row * N + col] = v;
        }
    }
}

// ---------------------------------------------------------------------------
// G = A A^T (64x64), then Gauss-Jordan inverse (well-conditioned Wishart,
// cond ~9, no pivoting needed). Single block.
// ---------------------------------------------------------------------------
__global__ __launch_bounds__(256) void aat_inv_kernel(const float* __restrict__ A)
{
    __shared__ float Wk[M_CON][2 * M_CON];   // augmented [G | I], 32KB
    __shared__ float fcol[M_CON];
    const int tid = threadIdx.x;

    for (int idx = tid; idx < M_CON * M_CON; idx += 256) {
        int r = idx >> 6, c = idx & 63;
        float s = 0.0f;
        for (int d = 0; d < D_DIM; d++)
            s = fmaf(A[r * D_DIM + d], A[c * D_DIM + d], s);
        Wk[r][c] = s;
        Wk[r][M_CON + c] = (r == c) ? 1.0f : 0.0f;
    }
    __syncthreads();

    for (int k = 0; k < M_CON; k++) {
        if (tid < M_CON) fcol[tid] = Wk[tid][k];
        __syncthreads();
        float pivinv = 1.0f / fcol[k];
        if (tid < 2 * M_CON) Wk[k][tid] *= pivinv;
        __syncthreads();
        for (int idx = tid; idx < M_CON * 2 * M_CON; idx += 256) {
            int r = idx >> 7, c = idx & 127;
            if (r != k) Wk[r][c] = fmaf(-fcol[r], Wk[k][c], Wk[r][c]);
        }
        __syncthreads();
    }

    for (int idx = tid; idx < M_CON * M_CON; idx += 256) {
        int r = idx >> 6, c = idx & 63;
        g_Ginv[idx] = Wk[r][M_CON + c];
    }
}

// Mop[m][d] = sum_j Ginv[m][j] * A[j][d]
__global__ __launch_bounds__(256) void mop_kernel(const float* __restrict__ A)
{
    int m = blockIdx.x, d = threadIdx.x;
    float s = 0.0f;
    #pragma unroll 8
    for (int j = 0; j < M_CON; j++)
        s = fmaf(g_Ginv[m * M_CON + j], A[j * D_DIM + d], s);
    g_Mop[m * D_DIM + d] = s;
}

// ---------------------------------------------------------------------------
// Persistent DR iteration kernel. Each block: TR=32 rows, 100 iterations
// entirely in registers + shared memory. Thread t owns column d=t of every
// row (z, y0, y in registers).
//   t = (z + y0)/2
//   s = t A^T - bcon          (phase 2, threads mapped (m, row-group))
//   y = t - s Mop             (phase 3, threads mapped to d)
//   w = max(2y - z, 0);  z += 1.7 (w - y)
// ---------------------------------------------------------------------------
#define SAT_OFF 0                         // sAT[d][m]  : 256*64
#define SMOP_OFF (SAT_OFF + 256 * 64)     // sM[m][d]   : 64*256
#define TS_OFF  (SMOP_OFF + 64 * 256)     // tS[r][d]   : 32*256
#define SS_OFF  (TS_OFF + 32 * 256)       // sS[r][m]   : 32*64
#define BC_OFF  (SS_OFF + 32 * 64)        // bc[r][m]   : 32*64
#define ITER_SMEM_FLOATS (BC_OFF + 32 * 64)
#define ITER_SMEM_BYTES (ITER_SMEM_FLOATS * 4)

__global__ __launch_bounds__(256, 1) void iterate_kernel(
    const float* __restrict__ bcon, const float* __restrict__ A,
    const float* __restrict__ y0g, float* __restrict__ out)
{
    extern __shared__ float sm[];
    float* sAT = sm + SAT_OFF;
    float* sM  = sm + SMOP_OFF;
    float* tS  = sm + TS_OFF;
    float* sS  = sm + SS_OFF;
    float* bc  = sm + BC_OFF;

    const int tid  = threadIdx.x;
    const int row0 = blockIdx.x * TR;

    // stage operands
    for (int i = tid; i < M_CON * D_DIM; i += 256) {
        int m = i >> 8, d = i & 255;            // A is [64][256] row-major
        sAT[d * M_CON + m] = A[i];
    }
    for (int i = tid; i < M_CON * D_DIM; i += 256) sM[i] = g_Mop[i];
    for (int i = tid; i < TR * M_CON; i += 256)   bc[i] = bcon[row0 * M_CON + i];

    float z[TR], y0r[TR], acc[TR];
    #pragma unroll
    for (int r = 0; r < TR; r++) {
        y0r[r] = y0g[(size_t)(row0 + r) * D_DIM + tid];
        z[r]   = y0r[r];
    }
    __syncthreads();

    const int mi = tid & 63;     // constraint index
    const int rg = tid >> 6;     // row group: rows rg*8 .. rg*8+7

    #pragma unroll 1
    for (int it = 0; it < N_ITER; it++) {
        // ---- phase 1: t = (z + y0) * 0.5 (sigma = 1) ----
        #pragma unroll
        for (int r = 0; r < TR; r++)
            tS[r * D_DIM + tid] = (z[r] + y0r[r]) * 0.5f;
        __syncthreads();

        // ---- phase 2: s[r][mi] = t[r] . A[mi] - bcon[r][mi] ----
        float a8[8];
        #pragma unroll
        for (int j = 0; j < 8; j++) a8[j] = -bc[(rg * 8 + j) * M_CON + mi];
        #pragma unroll 4
        for (int d = 0; d < D_DIM; d += 4) {
            float w0 = sAT[(d + 0) * M_CON + mi];
            float w1 = sAT[(d + 1) * M_CON + mi];
            float w2 = sAT[(d + 2) * M_CON + mi];
            float w3 = sAT[(d + 3) * M_CON + mi];
            #pragma unroll
            for (int j = 0; j < 8; j++) {
                float4 tv = *(const float4*)&tS[(rg * 8 + j) * D_DIM + d];
                float v = a8[j];
                v = fmaf(tv.x, w0, v);
                v = fmaf(tv.y, w1, v);
                v = fmaf(tv.z, w2, v);
                v = fmaf(tv.w, w3, v);
                a8[j] = v;
            }
        }
        #pragma unroll
        for (int j = 0; j < 8; j++) sS[(rg * 8 + j) * M_CON + mi] = a8[j];
        __syncthreads();

        // ---- phase 3: y[r][tid] = t[r][tid] - sum_m s[r][m] * Mop[m][tid] ----
        #pragma unroll
        for (int r = 0; r < TR; r++) acc[r] = (z[r] + y0r[r]) * 0.5f;
        #pragma unroll 2
        for (int m = 0; m < M_CON; m += 4) {
            float q0 = sM[(m + 0) * D_DIM + tid];
            float q1 = sM[(m + 1) * D_DIM + tid];
            float q2 = sM[(m + 2) * D_DIM + tid];
            float q3 = sM[(m + 3) * D_DIM + tid];
            #pragma unroll
            for (int r = 0; r < TR; r++) {
                float4 sv = *(const float4*)&sS[r * M_CON + m];
                float v = acc[r];
                v = fmaf(-sv.x, q0, v);
                v = fmaf(-sv.y, q1, v);
                v = fmaf(-sv.z, q2, v);
                v = fmaf(-sv.w, q3, v);
                acc[r] = v;
            }
        }

        // ---- phase 4: w = max(2y - z, 0);  z += omega * (w - y) ----
        #pragma unroll
        for (int r = 0; r < TR; r++) {
            float y = acc[r];
            float w = fmaxf(2.0f * y - z[r], 0.0f);
            z[r] = fmaf(1.7f, w - y, z[r]);
        }
    }

    #pragma unroll
    for (int r = 0; r < TR; r++)
        out[(size_t)(row0 + r) * D_DIM + tid] = acc[r];
}

// ---------------------------------------------------------------------------
extern "C" void kernel_launch(void* const* d_in, const int* in_sizes, int n_in,
                              void* d_out, int out_size)
{
    const float* x    = (const float*)d_in[0];
    const float* bcon = (const float*)d_in[1];
    const float* A    = (const float*)d_in[2];
    const float* W1   = (const float*)d_in[3];
    const float* b1   = (const float*)d_in[4];
    const float* W2   = (const float*)d_in[5];
    const float* b2   = (const float*)d_in[6];
    const float* W3   = (const float*)d_in[7];
    const float* b3   = (const float*)d_in[8];
    const float* Wout = (const float*)d_in[9];
    const float* bout = (const float*)d_in[10];
    float* out = (float*)d_out;

    float *h1, *h2, *y0;
    cudaGetSymbolAddress((void**)&h1, g_h1);
    cudaGetSymbolAddress((void**)&h2, g_h2);
    cudaGetSymbolAddress((void**)&y0, g_y0);

    static int smem_set = 0;
    if (!smem_set) {
        cudaFuncSetAttribute(iterate_kernel,
                             cudaFuncAttributeMaxDynamicSharedMemorySize,
                             ITER_SMEM_BYTES);
        smem_set = 1;
    }

    dim3 blk(256);
    // MLP trunk
    gemm_bias_act<<<dim3(H_DIM / 128, B_ROWS / 128), blk>>>(x,  W1, b1, h1, B_ROWS, H_DIM, DIM_IN, 1);
    gemm_bias_act<<<dim3(H_DIM / 128, B_ROWS / 128), blk>>>(h1, W2, b2, h2, B_ROWS, H_DIM, H_DIM, 1);
    gemm_bias_act<<<dim3(H_DIM / 128, B_ROWS / 128), blk>>>(h2, W3, b3, h1, B_ROWS, H_DIM, H_DIM, 1);
    gemm_bias_act<<<dim3(D_DIM / 128, B_ROWS / 128), blk>>>(h1, Wout, bout, y0, B_ROWS, D_DIM, H_DIM, 0);

    // projection operator setup
    aat_inv_kernel<<<1, 256>>>(A);
    mop_kernel<<<M_CON, D_DIM>>>(A);

    // 100 Douglas-Rachford iterations, persistent
    iterate_kernel<<<B_ROWS / TR, 256, ITER_SMEM_BYTES>>>(bcon, A, y0, out);
}

// round 7
// speedup vs baseline: 1.0303x; 1.0303x over previous
#include <cuda_runtime.h>

// Problem constants (fixed by the dataset)
#define B_ROWS 4096
#define DIM_IN 128
#define H_DIM  512
#define D_DIM  256
#define M_CON  64
#define N_ITER 100
#define TR     32          // rows per block in the iteration kernel

// Scratch (device globals: no allocation allowed)
__device__ float g_h1[B_ROWS * H_DIM];
__device__ float g_h2[B_ROWS * H_DIM];
__device__ float g_y0[B_ROWS * D_DIM];
__device__ float g_Ginv[M_CON * M_CON];
__device__ float g_Mop[M_CON * D_DIM];

// ---------------------------------------------------------------------------
// Packed fp32x2 helpers (SASS FFMA2 — ptxas never auto-generates these)
// ---------------------------------------------------------------------------
__device__ __forceinline__ unsigned long long pack2(float lo, float hi) {
    unsigned long long r;
    asm("mov.b64 %0, {%1, %2};" : "=l"(r) : "f"(lo), "f"(hi));
    return r;
}
__device__ __forceinline__ unsigned long long dup2(float v) {
    unsigned long long r;
    asm("mov.b64 %0, {%1, %1};" : "=l"(r) : "f"(v));
    return r;
}
__device__ __forceinline__ void fma2(unsigned long long& d,
                                     unsigned long long a,
                                     unsigned long long b) {
    asm("fma.rn.f32x2 %0, %1, %2, %0;" : "+l"(d) : "l"(a), "l"(b));
}
__device__ __forceinline__ void unpack2(unsigned long long v, float& lo, float& hi) {
    asm("mov.b64 {%0, %1}, %2;" : "=f"(lo), "=f"(hi) : "l"(v));
}

// ---------------------------------------------------------------------------
// Register-blocked SGEMM with packed FFMA2: C = act(X @ W + bias)
// BM=BN=128, BK=16, 256 threads, 8x8 per thread (accumulated as 8x4 f32x2).
// ---------------------------------------------------------------------------
__global__ __launch_bounds__(256) void gemm_bias_act(
    const float* __restrict__ X, const float* __restrict__ W,
    const float* __restrict__ bias, float* __restrict__ C,
    int M, int N, int K, int doRelu)
{
    __shared__ float Xs[16][128];
    __shared__ float Ws[16][128];

    const int tid  = threadIdx.x;
    const int brow = blockIdx.y * 128;
    const int bcol = blockIdx.x * 128;
    const int tx   = tid & 15;   // n-dir, 8 cols
    const int ty   = tid >> 4;   // m-dir, 8 rows

    const int xr0 = tid >> 2;
    const int xc0 = (tid & 3) * 4;
    const int wr0 = tid >> 5;
    const int wc0 = (tid & 31) * 4;

    unsigned long long acc2[8][4];
    #pragma unroll
    for (int i = 0; i < 8; i++)
        #pragma unroll
        for (int j = 0; j < 4; j++) acc2[i][j] = 0ULL;

    for (int kt = 0; kt < K; kt += 16) {
        float4 xv0 = *(const float4*)&X[(size_t)(brow + xr0) * K + kt + xc0];
        float4 xv1 = *(const float4*)&X[(size_t)(brow + xr0 + 64) * K + kt + xc0];
        float4 wv0 = *(const float4*)&W[(size_t)(kt + wr0) * N + bcol + wc0];
        float4 wv1 = *(const float4*)&W[(size_t)(kt + wr0 + 8) * N + bcol + wc0];

        Xs[xc0 + 0][xr0] = xv0.x;  Xs[xc0 + 1][xr0] = xv0.y;
        Xs[xc0 + 2][xr0] = xv0.z;  Xs[xc0 + 3][xr0] = xv0.w;
        Xs[xc0 + 0][xr0 + 64] = xv1.x;  Xs[xc0 + 1][xr0 + 64] = xv1.y;
        Xs[xc0 + 2][xr0 + 64] = xv1.z;  Xs[xc0 + 3][xr0 + 64] = xv1.w;
        *(float4*)&Ws[wr0][wc0]     = wv0;
        *(float4*)&Ws[wr0 + 8][wc0] = wv1;
        __syncthreads();

        #pragma unroll
        for (int k = 0; k < 16; k++) {
            float a[8];
            float4 a0 = *(const float4*)&Xs[k][ty * 8];
            float4 a1 = *(const float4*)&Xs[k][ty * 8 + 4];
            a[0]=a0.x; a[1]=a0.y; a[2]=a0.z; a[3]=a0.w;
            a[4]=a1.x; a[5]=a1.y; a[6]=a1.z; a[7]=a1.w;
            const ulonglong2* bp = (const ulonglong2*)&Ws[k][tx * 8];
            ulonglong2 bA = bp[0];
            ulonglong2 bB = bp[1];
            #pragma unroll
            for (int i = 0; i < 8; i++) {
                unsigned long long ad = dup2(a[i]);
                fma2(acc2[i][0], ad, bA.x);
                fma2(acc2[i][1], ad, bA.y);
                fma2(acc2[i][2], ad, bB.x);
                fma2(acc2[i][3], ad, bB.y);
            }
        }
        __syncthreads();
    }

    #pragma unroll
    for (int i = 0; i < 8; i++) {
        int row = brow + ty * 8 + i;
        #pragma unroll
        for (int j = 0; j < 4; j++) {
            float v0, v1;
            unpack2(acc2[i][j], v0, v1);
            int col = bcol + tx * 8 + j * 2;
            v0 += bias[col];
            v1 += bias[col + 1];
            if (doRelu) { v0 = fmaxf(v0, 0.0f); v1 = fmaxf(v1, 0.0f); }
            C[(size_t)row * N + col]     = v0;
            C[(size_t)row * N + col + 1] = v1;
        }
    }
}

// ---------------------------------------------------------------------------
// G = A A^T (64x64), then Gauss-Jordan inverse (well-conditioned Wishart).
// ---------------------------------------------------------------------------
__global__ __launch_bounds__(256) void aat_inv_kernel(const float* __restrict__ A)
{
    __shared__ float Wk[M_CON][2 * M_CON];
    __shared__ float fcol[M_CON];
    const int tid = threadIdx.x;

    for (int idx = tid; idx < M_CON * M_CON; idx += 256) {
        int r = idx >> 6, c = idx & 63;
        float s = 0.0f;
        for (int d = 0; d < D_DIM; d++)
            s = fmaf(A[r * D_DIM + d], A[c * D_DIM + d], s);
        Wk[r][c] = s;
        Wk[r][M_CON + c] = (r == c) ? 1.0f : 0.0f;
    }
    __syncthreads();

    for (int k = 0; k < M_CON; k++) {
        if (tid < M_CON) fcol[tid] = Wk[tid][k];
        __syncthreads();
        float pivinv = 1.0f / fcol[k];
        if (tid < 2 * M_CON) Wk[k][tid] *= pivinv;
        __syncthreads();
        for (int idx = tid; idx < M_CON * 2 * M_CON; idx += 256) {
            int r = idx >> 7, c = idx & 127;
            if (r != k) Wk[r][c] = fmaf(-fcol[r], Wk[k][c], Wk[r][c]);
        }
        __syncthreads();
    }

    for (int idx = tid; idx < M_CON * M_CON; idx += 256) {
        int r = idx >> 6, c = idx & 63;
        g_Ginv[idx] = Wk[r][M_CON + c];
    }
}

// Mop[m][d] = sum_j Ginv[m][j] * A[j][d]
__global__ __launch_bounds__(256) void mop_kernel(const float* __restrict__ A)
{
    int m = blockIdx.x, d = threadIdx.x;
    float s = 0.0f;
    #pragma unroll 8
    for (int j = 0; j < M_CON; j++)
        s = fmaf(g_Ginv[m * M_CON + j], A[j * D_DIM + d], s);
    g_Mop[m * D_DIM + d] = s;
}

// ---------------------------------------------------------------------------
// Persistent DR iteration kernel, FFMA2-packed over row pairs.
// Row-pair-interleaved shared layouts so packed operands come straight from
// 64-bit shared loads:
//   tS2[p][d]  : float2 {t[2p][d],  t[2p+1][d]}    (16 pairs x 256)
//   sS2[p][m]  : float2 {s[2p][m],  s[2p+1][m]}    (16 pairs x 64)
//   bc2[p][m]  : float2 {-bc[2p][m],-bc[2p+1][m]}  (pre-negated)
// ---------------------------------------------------------------------------
#define SAT_OFF 0                          // sAT[d][m]  : 256*64
#define SMOP_OFF (SAT_OFF + 256 * 64)      // sM[m][d]   : 64*256
#define TS_OFF  (SMOP_OFF + 64 * 256)      // tS2        : 16*256*2
#define SS_OFF  (TS_OFF + 16 * 256 * 2)    // sS2        : 16*64*2
#define BC_OFF  (SS_OFF + 16 * 64 * 2)     // bc2        : 16*64*2
#define ITER_SMEM_FLOATS (BC_OFF + 16 * 64 * 2)
#define ITER_SMEM_BYTES (ITER_SMEM_FLOATS * 4)

__global__ __launch_bounds__(256, 1) void iterate_kernel(
    const float* __restrict__ bcon, const float* __restrict__ A,
    const float* __restrict__ y0g, float* __restrict__ out)
{
    extern __shared__ float sm[];
    float* sAT = sm + SAT_OFF;
    float* sM  = sm + SMOP_OFF;
    float* tS2 = sm + TS_OFF;
    float* sS2 = sm + SS_OFF;
    float* bc2 = sm + BC_OFF;

    const int tid  = threadIdx.x;
    const int row0 = blockIdx.x * TR;

    // stage operands
    for (int i = tid; i < M_CON * D_DIM; i += 256) {
        int m = i >> 8, d = i & 255;               // A is [64][256] row-major
        sAT[d * M_CON + m] = A[i];
    }
    for (int i = tid; i < M_CON * D_DIM; i += 256) sM[i] = g_Mop[i];
    for (int i = tid; i < TR * M_CON; i += 256) {
        int r = i >> 6, m = i & 63;
        int p = r >> 1, h = r & 1;
        bc2[(p * M_CON + m) * 2 + h] = -bcon[(size_t)(row0 + r) * M_CON + m];
    }

    float z[TR], y0r[TR];
    #pragma unroll
    for (int r = 0; r < TR; r++) {
        y0r[r] = y0g[(size_t)(row0 + r) * D_DIM + tid];
        z[r]   = y0r[r];
    }
    __syncthreads();

    const int mi = tid & 63;     // constraint index
    const int rg = tid >> 6;     // pair group: pairs rg*4 .. rg*4+3

    unsigned long long acc2[TR / 2];   // packed row-pair accumulators (y / t)

    #pragma unroll 1
    for (int it = 0; it < N_ITER; it++) {
        // ---- phase 1: t = (z + y0) * 0.5 ; pack pairs, keep in regs + smem ----
        #pragma unroll
        for (int p = 0; p < TR / 2; p++) {
            float t0 = (z[2 * p]     + y0r[2 * p])     * 0.5f;
            float t1 = (z[2 * p + 1] + y0r[2 * p + 1]) * 0.5f;
            unsigned long long tp = pack2(t0, t1);
            acc2[p] = tp;
            *(unsigned long long*)&tS2[(p * D_DIM + tid) * 2] = tp;
        }
        __syncthreads();

        // ---- phase 2: s[pair][mi] = t[pair] . A[mi] - bc[pair][mi] (packed) ----
        {
            unsigned long long a2[4];
            #pragma unroll
            for (int j = 0; j < 4; j++)
                a2[j] = *(const unsigned long long*)&bc2[((rg * 4 + j) * M_CON + mi) * 2];
            #pragma unroll 4
            for (int d = 0; d < D_DIM; d += 4) {
                unsigned long long w0 = dup2(sAT[(d + 0) * M_CON + mi]);
                unsigned long long w1 = dup2(sAT[(d + 1) * M_CON + mi]);
                unsigned long long w2 = dup2(sAT[(d + 2) * M_CON + mi]);
                unsigned long long w3 = dup2(sAT[(d + 3) * M_CON + mi]);
                #pragma unroll
                for (int j = 0; j < 4; j++) {
                    const ulonglong2* tp =
                        (const ulonglong2*)&tS2[((rg * 4 + j) * D_DIM + d) * 2];
                    ulonglong2 vA = tp[0];   // pairs for d, d+1
                    ulonglong2 vB = tp[1];   // pairs for d+2, d+3
                    fma2(a2[j], vA.x, w0);
                    fma2(a2[j], vA.y, w1);
                    fma2(a2[j], vB.x, w2);
                    fma2(a2[j], vB.y, w3);
                }
            }
            #pragma unroll
            for (int j = 0; j < 4; j++)
                *(unsigned long long*)&sS2[((rg * 4 + j) * M_CON + mi) * 2] = a2[j];
        }
        __syncthreads();

        // ---- phase 3: y[pair][tid] = t[pair][tid] - sum_m s[pair][m]*Mop[m][tid] ----
        #pragma unroll 2
        for (int m = 0; m < M_CON; m += 4) {
            unsigned long long q0 = dup2(-sM[(m + 0) * D_DIM + tid]);
            unsigned long long q1 = dup2(-sM[(m + 1) * D_DIM + tid]);
            unsigned long long q2 = dup2(-sM[(m + 2) * D_DIM + tid]);
            unsigned long long q3 = dup2(-sM[(m + 3) * D_DIM + tid]);
            #pragma unroll
            for (int p = 0; p < TR / 2; p++) {
                const ulonglong2* sp = (const ulonglong2*)&sS2[(p * M_CON + m) * 2];
                ulonglong2 sA = sp[0];   // pairs for m, m+1
                ulonglong2 sB = sp[1];   // pairs for m+2, m+3
                fma2(acc2[p], sA.x, q0);
                fma2(acc2[p], sA.y, q1);
                fma2(acc2[p], sB.x, q2);
                fma2(acc2[p], sB.y, q3);
            }
        }

        // ---- phase 4: w = max(2y - z, 0);  z += omega * (w - y) ----
        #pragma unroll
        for (int p = 0; p < TR / 2; p++) {
            float ya, yb;
            unpack2(acc2[p], ya, yb);
            float wa = fmaxf(2.0f * ya - z[2 * p], 0.0f);
            float wb = fmaxf(2.0f * yb - z[2 * p + 1], 0.0f);
            z[2 * p]     = fmaf(1.7f, wa - ya, z[2 * p]);
            z[2 * p + 1] = fmaf(1.7f, wb - yb, z[2 * p + 1]);
        }
    }

    #pragma unroll
    for (int p = 0; p < TR / 2; p++) {
        float ya, yb;
        unpack2(acc2[p], ya, yb);
        out[(size_t)(row0 + 2 * p)     * D_DIM + tid] = ya;
        out[(size_t)(row0 + 2 * p + 1) * D_DIM + tid] = yb;
    }
}

// ---------------------------------------------------------------------------
extern "C" void kernel_launch(void* const* d_in, const int* in_sizes, int n_in,
                              void* d_out, int out_size)
{
    const float* x    = (const float*)d_in[0];
    const float* bcon = (const float*)d_in[1];
    const float* A    = (const float*)d_in[2];
    const float* W1   = (const float*)d_in[3];
    const float* b1   = (const float*)d_in[4];
    const float* W2   = (const float*)d_in[5];
    const float* b2   = (const float*)d_in[6];
    const float* W3   = (const float*)d_in[7];
    const float* b3   = (const float*)d_in[8];
    const float* Wout = (const float*)d_in[9];
    const float* bout = (const float*)d_in[10];
    float* out = (float*)d_out;

    float *h1, *h2, *y0;
    cudaGetSymbolAddress((void**)&h1, g_h1);
    cudaGetSymbolAddress((void**)&h2, g_h2);
    cudaGetSymbolAddress((void**)&y0, g_y0);

    cudaFuncSetAttribute(iterate_kernel,
                         cudaFuncAttributeMaxDynamicSharedMemorySize,
                         ITER_SMEM_BYTES);

    dim3 blk(256);
    // MLP trunk
    gemm_bias_act<<<dim3(H_DIM / 128, B_ROWS / 128), blk>>>(x,  W1, b1, h1, B_ROWS, H_DIM, DIM_IN, 1);
    gemm_bias_act<<<dim3(H_DIM / 128, B_ROWS / 128), blk>>>(h1, W2, b2, h2, B_ROWS, H_DIM, H_DIM, 1);
    gemm_bias_act<<<dim3(H_DIM / 128, B_ROWS / 128), blk>>>(h2, W3, b3, h1, B_ROWS, H_DIM, H_DIM, 1);
    gemm_bias_act<<<dim3(D_DIM / 128, B_ROWS / 128), blk>>>(h1, Wout, bout, y0, B_ROWS, D_DIM, H_DIM, 0);

    // projection operator setup
    aat_inv_kernel<<<1, 256>>>(A);
    mop_kernel<<<M_CON, D_DIM>>>(A);

    // 100 Douglas-Rachford iterations, persistent
    iterate_kernel<<<B_ROWS / TR, 256, ITER_SMEM_BYTES>>>(bcon, A, y0, out);
}